// round 15
// baseline (speedup 1.0000x reference)
#include <cuda_runtime.h>
#include <stdint.h>

#define N_NODES 50000
#define N_PAD   50048   // multiple of 128 for k_h2 tiling
#define N_EDGES 800000
#define HID     128
#define OUTC    64

// ---- scratch (device globals, zero-initialized at module load; k_gather2
//      re-zeroes g_deg/g_total/g_v each call so every replay starts clean).
//      Node arrays padded to N_PAD; pad entries stay 0. ----
__device__ int   g_deg[N_PAD];
__device__ int   g_rowstart[N_PAD];
__device__ int   g_wpos[N_PAD];
__device__ int   g_csrc[N_EDGES];
__device__ int   g_total;
__device__ float g_dinv[N_PAD];
__device__ __align__(16) float    g_xw[N_PAD * 4];     // x * dinv, packed float4
__device__ __align__(16) float    g_v[N_PAD * 4];      // layer-1 edge sums (RED target)
__device__ __align__(16) uint32_t g_h2wb[N_PAD * 32];  // h2 * dinv, bf16x2 pairs

#define PACK2(d, lo, hi) asm("mov.b64 %0, {%1, %2};" : "=l"(d) : "f"(lo), "f"(hi))
#define UNPACK2(lo, hi, s) asm("mov.b64 {%0, %1}, %2;" : "=f"(lo), "=f"(hi) : "l"(s))
#define FMA2(d, a, b, c) asm("fma.rn.f32x2 %0, %1, %2, %3;" : "=l"(d) : "l"(a), "l"(b), "l"(c))
// u = {hi: bf16(hiF), lo: bf16(loF)}
#define BF16X2(u, hiF, loF) asm("cvt.rn.bf16x2.f32 %0, %1, %2;" : "=r"(u) : "f"(hiF), "f"(loF))

// 1) degree histogram on dst (REDG, no return); 2 edges/thread (best measured)
__global__ void k_deg(const int* __restrict__ ei) {
    int t = blockIdx.x * blockDim.x + threadIdx.x;
    if (t >= N_EDGES / 2) return;
    int2 d = ((const int2*)(ei + N_EDGES))[t];
    atomicAdd(&g_deg[d.x], 1);
    atomicAdd(&g_deg[d.y], 1);
}

// 2) row allocation (warp scan + 1 atomic/warp) + dinv + premultiplied xw
__global__ void k_assign(const float* __restrict__ x) {
    int i = blockIdx.x * blockDim.x + threadIdx.x;
    int lane = threadIdx.x & 31;
    int deg = (i < N_NODES) ? g_deg[i] : 0;
    int incl = deg;
    #pragma unroll
    for (int o = 1; o < 32; o <<= 1) {
        int v = __shfl_up_sync(0xffffffff, incl, o);
        if (lane >= o) incl += v;
    }
    int base = 0;
    if (lane == 31) base = atomicAdd(&g_total, incl);   // incl@31 = warp total
    base = __shfl_sync(0xffffffff, base, 31);
    if (i < N_NODES) {
        int rs = base + incl - deg;
        g_rowstart[i] = rs;
        g_wpos[i] = rs;
        float dd = rsqrtf((float)(deg + 1));
        g_dinv[i] = dd;
        float4 xw;
        xw.x = __ldg(&x[i * 3 + 0]) * dd;
        xw.y = __ldg(&x[i * 3 + 1]) * dd;
        xw.z = __ldg(&x[i * 3 + 2]) * dd;
        xw.w = 0.f;
        ((float4*)g_xw)[i] = xw;
    }
}

// 3) FUSED CSR scatter + layer-1 scatter-aggregation (order-free v4 REDs)
__global__ void k_csr(const int* __restrict__ ei) {
    int t = blockIdx.x * blockDim.x + threadIdx.x;
    if (t >= N_EDGES / 2) return;
    int2 s = ((const int2*)ei)[t];
    int2 d = ((const int2*)(ei + N_EDGES))[t];
    int p0 = atomicAdd(&g_wpos[d.x], 1);
    int p1 = atomicAdd(&g_wpos[d.y], 1);
    float4 v0 = ((const float4*)g_xw)[s.x];
    float4 v1 = ((const float4*)g_xw)[s.y];
    g_csrc[p0] = s.x;
    g_csrc[p1] = s.y;
    float* q0 = g_v + (size_t)d.x * 4;
    float* q1 = g_v + (size_t)d.y * 4;
    asm volatile("red.global.add.v4.f32 [%0], {%1,%2,%3,%4};"
                 :: "l"(q0), "f"(v0.x), "f"(v0.y), "f"(v0.z), "f"(0.f) : "memory");
    asm volatile("red.global.add.v4.f32 [%0], {%1,%2,%3,%4};"
                 :: "l"(q1), "f"(v1.x), "f"(v1.y), "f"(v1.z), "f"(0.f) : "memory");
}

// 4) fused: v=(g_v+xw_self)*dinv + h1 = relu(v@W1+b1) staged DUPLICATED
//    ((h,h) 64-bit words, [k][node]) in FOUR 32-k chunks + h2 = h1 @ W2 via
//    fma.rn.f32x2 packed over COLUMN pairs — both operands load as native
//    64-bit pairs: zero movs in the mainloop.
__global__ void __launch_bounds__(256, 3) k_h2(const float* __restrict__ W1,
                                               const float* __restrict__ b1,
                                               const float* __restrict__ W2) {
    __shared__ float4 sW2[HID * 16];                 // 32 KB, all k
    __shared__ unsigned long long sh1Td[32 * 128];   // 32 KB, [k_local][node] (h,h)
    __shared__ float4 sv[128];                       // 2 KB
    int tid = threadIdx.x;
    int nodeBase = blockIdx.x * 128;

    #pragma unroll 4
    for (int i = tid; i < HID * 16; i += 256) sW2[i] = ((const float4*)W2)[i];

    if (tid < 128) {                    // finalize layer-1 vector per node
        int gnode = nodeBase + tid;     // pad nodes: all zeros -> sv = 0
        float4 gv = ((const float4*)g_v)[gnode];
        float4 xs = ((const float4*)g_xw)[gnode];
        float dd  = g_dinv[gnode];
        sv[tid] = make_float4((gv.x + xs.x) * dd,
                              (gv.y + xs.y) * dd,
                              (gv.z + xs.z) * dd, 0.f);
    }
    __syncthreads();

    int c  = tid & 15;        // cols 4c..4c+3 (2 col-pairs)
    int m0 = (tid >> 4) * 8;  // nodes m0..m0+7

    // acc[j][cp]: j = local node 0..7 (m0+j), cp = col pair (4c+2cp, 4c+2cp+1)
    unsigned long long acc[8][2];
    #pragma unroll
    for (int j = 0; j < 8; j++) { acc[j][0] = 0ull; acc[j][1] = 0ull; }

    const ulonglong2* sW2v = (const ulonglong2*)sW2;      // [k*16 + c]
    const ulonglong2* shv  = (const ulonglong2*)sh1Td;    // [k*64 + node/2]

    #pragma unroll
    for (int chunk = 0; chunk < 4; chunk++) {
        int qbase = chunk * 8;          // 8 k-quads per chunk (32 k)

        // h1 phase for k in [chunk*32, chunk*32+32): write (h,h) dup words
        #pragma unroll
        for (int i = tid; i < 128 * 8; i += 256) {
            int node = i & 127;
            int ql   = i >> 7;          // local quad 0..7
            int q    = qbase + ql;
            float4 v  = sv[node];
            float4 w0 = __ldg(&((const float4*)W1)[0 * 32 + q]);
            float4 w1 = __ldg(&((const float4*)W1)[1 * 32 + q]);
            float4 w2 = __ldg(&((const float4*)W1)[2 * 32 + q]);
            float4 bq = __ldg(&((const float4*)b1)[q]);
            float h0 = fmaxf(fmaf(v.x, w0.x, fmaf(v.y, w1.x, fmaf(v.z, w2.x, bq.x))), 0.f);
            float h1 = fmaxf(fmaf(v.x, w0.y, fmaf(v.y, w1.y, fmaf(v.z, w2.y, bq.y))), 0.f);
            float h2 = fmaxf(fmaf(v.x, w0.z, fmaf(v.y, w1.z, fmaf(v.z, w2.z, bq.z))), 0.f);
            float h3 = fmaxf(fmaf(v.x, w0.w, fmaf(v.y, w1.w, fmaf(v.z, w2.w, bq.w))), 0.f);
            unsigned long long p0, p1, p2, p3;
            PACK2(p0, h0, h0);
            PACK2(p1, h1, h1);
            PACK2(p2, h2, h2);
            PACK2(p3, h3, h3);
            sh1Td[(4 * ql + 0) * 128 + node] = p0;
            sh1Td[(4 * ql + 1) * 128 + node] = p1;
            sh1Td[(4 * ql + 2) * 128 + node] = p2;
            sh1Td[(4 * ql + 3) * 128 + node] = p3;
        }
        __syncthreads();

        // mainloop over this chunk's 32 k — zero movs, 5 LDS + 16 FMA2 per k
        #pragma unroll 4
        for (int kl = 0; kl < 32; kl++) {
            int kg = chunk * 32 + kl;               // global k
            ulonglong2 w = sW2v[kg * 16 + c];       // w.x=(c0,c1) w.y=(c2,c3)
            ulonglong2 h01 = shv[kl * 64 + (m0 >> 1) + 0];  // nodes m0,m0+1
            ulonglong2 h23 = shv[kl * 64 + (m0 >> 1) + 1];
            ulonglong2 h45 = shv[kl * 64 + (m0 >> 1) + 2];
            ulonglong2 h67 = shv[kl * 64 + (m0 >> 1) + 3];
            FMA2(acc[0][0], h01.x, w.x, acc[0][0]);
            FMA2(acc[0][1], h01.x, w.y, acc[0][1]);
            FMA2(acc[1][0], h01.y, w.x, acc[1][0]);
            FMA2(acc[1][1], h01.y, w.y, acc[1][1]);
            FMA2(acc[2][0], h23.x, w.x, acc[2][0]);
            FMA2(acc[2][1], h23.x, w.y, acc[2][1]);
            FMA2(acc[3][0], h23.y, w.x, acc[3][0]);
            FMA2(acc[3][1], h23.y, w.y, acc[3][1]);
            FMA2(acc[4][0], h45.x, w.x, acc[4][0]);
            FMA2(acc[4][1], h45.x, w.y, acc[4][1]);
            FMA2(acc[5][0], h45.y, w.x, acc[5][0]);
            FMA2(acc[5][1], h45.y, w.y, acc[5][1]);
            FMA2(acc[6][0], h67.x, w.x, acc[6][0]);
            FMA2(acc[6][1], h67.x, w.y, acc[6][1]);
            FMA2(acc[7][0], h67.y, w.x, acc[7][0]);
            FMA2(acc[7][1], h67.y, w.y, acc[7][1]);
        }
        __syncthreads();    // sh1Td reused next chunk
    }

    // epilogue: scale by dinv, convert to bf16 pairs, store
    #pragma unroll
    for (int j = 0; j < 8; j++) {
        int n = nodeBase + m0 + j;
        float dd = g_dinv[n];
        float f0, f1, f2, f3;
        UNPACK2(f0, f1, acc[j][0]);     // cols 4c, 4c+1
        UNPACK2(f2, f3, acc[j][1]);     // cols 4c+2, 4c+3
        uint2 u;
        BF16X2(u.x, f1 * dd, f0 * dd);
        BF16X2(u.y, f3 * dd, f2 * dd);
        *(uint2*)&g_h2wb[(size_t)n * 32 + 2 * c] = u;
    }
}

// 5) layer-2 gather in bf16: 8 threads/node, each owns 8 cols (uint4 = 16B).
//    out = dinv[d]*(sum h2w[s] + h2w[d]) + b2. Resets deg/total/v for replay.
__global__ void k_gather2(const float* __restrict__ b2,
                          float* __restrict__ out) {
    int gid = blockIdx.x * blockDim.x + threadIdx.x;
    int node = gid >> 3;
    int q    = gid & 7;                 // uint32 words 4q..4q+3 = cols 8q..8q+7
    if (node >= N_NODES) return;
    int row = g_rowstart[node];
    int deg = g_deg[node];
    int end = row + deg;
    if (q == 0) {                       // reset for next call
        g_deg[node] = 0;
        ((float4*)g_v)[node] = make_float4(0.f, 0.f, 0.f, 0.f);
    }
    if (gid == 0) g_total = 0;

    float a[8];
    {   // self term
        uint4 u = *(const uint4*)&g_h2wb[(size_t)node * 32 + 4 * q];
        a[0] = __uint_as_float(u.x << 16);
        a[1] = __uint_as_float(u.x & 0xFFFF0000u);
        a[2] = __uint_as_float(u.y << 16);
        a[3] = __uint_as_float(u.y & 0xFFFF0000u);
        a[4] = __uint_as_float(u.z << 16);
        a[5] = __uint_as_float(u.z & 0xFFFF0000u);
        a[6] = __uint_as_float(u.w << 16);
        a[7] = __uint_as_float(u.w & 0xFFFF0000u);
    }
    int e = row;
    for (; e + 2 <= end; e += 2) {
        int s0 = g_csrc[e];
        int s1 = g_csrc[e + 1];
        uint4 u0 = *(const uint4*)&g_h2wb[(size_t)s0 * 32 + 4 * q];
        uint4 u1 = *(const uint4*)&g_h2wb[(size_t)s1 * 32 + 4 * q];
        a[0] += __uint_as_float(u0.x << 16)         + __uint_as_float(u1.x << 16);
        a[1] += __uint_as_float(u0.x & 0xFFFF0000u) + __uint_as_float(u1.x & 0xFFFF0000u);
        a[2] += __uint_as_float(u0.y << 16)         + __uint_as_float(u1.y << 16);
        a[3] += __uint_as_float(u0.y & 0xFFFF0000u) + __uint_as_float(u1.y & 0xFFFF0000u);
        a[4] += __uint_as_float(u0.z << 16)         + __uint_as_float(u1.z << 16);
        a[5] += __uint_as_float(u0.z & 0xFFFF0000u) + __uint_as_float(u1.z & 0xFFFF0000u);
        a[6] += __uint_as_float(u0.w << 16)         + __uint_as_float(u1.w << 16);
        a[7] += __uint_as_float(u0.w & 0xFFFF0000u) + __uint_as_float(u1.w & 0xFFFF0000u);
    }
    if (e < end) {
        uint4 u = *(const uint4*)&g_h2wb[(size_t)g_csrc[e] * 32 + 4 * q];
        a[0] += __uint_as_float(u.x << 16);
        a[1] += __uint_as_float(u.x & 0xFFFF0000u);
        a[2] += __uint_as_float(u.y << 16);
        a[3] += __uint_as_float(u.y & 0xFFFF0000u);
        a[4] += __uint_as_float(u.z << 16);
        a[5] += __uint_as_float(u.z & 0xFFFF0000u);
        a[6] += __uint_as_float(u.w << 16);
        a[7] += __uint_as_float(u.w & 0xFFFF0000u);
    }
    float dd = g_dinv[node];
    float4 bb0 = __ldg(&((const float4*)b2)[2 * q]);
    float4 bb1 = __ldg(&((const float4*)b2)[2 * q + 1]);
    float4 o0, o1;
    o0.x = fmaf(dd, a[0], bb0.x);
    o0.y = fmaf(dd, a[1], bb0.y);
    o0.z = fmaf(dd, a[2], bb0.z);
    o0.w = fmaf(dd, a[3], bb0.w);
    o1.x = fmaf(dd, a[4], bb1.x);
    o1.y = fmaf(dd, a[5], bb1.y);
    o1.z = fmaf(dd, a[6], bb1.z);
    o1.w = fmaf(dd, a[7], bb1.w);
    ((float4*)out)[(size_t)node * 16 + 2 * q] = o0;
    ((float4*)out)[(size_t)node * 16 + 2 * q + 1] = o1;
}

extern "C" void kernel_launch(void* const* d_in, const int* in_sizes, int n_in,
                              void* d_out, int out_size) {
    const float* x  = (const float*)d_in[0];
    const int*   ei = (const int*)d_in[1];   // int64 in ref -> int32 on device (JAX x64 off)
    const float* W1 = (const float*)d_in[2];
    const float* b1 = (const float*)d_in[3];
    const float* W2 = (const float*)d_in[4];
    const float* b2 = (const float*)d_in[5];
    float* out = (float*)d_out;

    k_deg<<<(N_EDGES / 2 + 255) / 256, 256>>>(ei);
    k_assign<<<(N_NODES + 255) / 256, 256>>>(x);
    k_csr<<<(N_EDGES / 2 + 255) / 256, 256>>>(ei);
    k_h2<<<N_PAD / 128, 256>>>(W1, b1, W2);
    k_gather2<<<(N_NODES * 8 + 255) / 256, 256>>>(b2, out);
}

// round 16
// speedup vs baseline: 1.0836x; 1.0836x over previous
#include <cuda_runtime.h>
#include <stdint.h>

#define N_NODES 50000
#define N_PAD   50048   // multiple of 128 for k_h2 tiling
#define N_EDGES 800000
#define HID     128
#define OUTC    64

// ---- scratch (device globals, zero-initialized at module load; k_gather2
//      re-zeroes g_deg/g_total/g_v each call so every replay starts clean).
//      Node arrays padded to N_PAD; pad entries stay 0. ----
__device__ int   g_deg[N_PAD];
__device__ int   g_rowstart[N_PAD];
__device__ int   g_wpos[N_PAD];
__device__ int   g_csrc[N_EDGES];
__device__ int   g_total;
__device__ float g_dinv[N_PAD];
__device__ __align__(16) float    g_xw[N_PAD * 4];     // x * dinv, packed float4
__device__ __align__(16) float    g_v[N_PAD * 4];      // layer-1 edge sums (RED target)
__device__ __align__(16) uint32_t g_h2wb[N_PAD * 32];  // h2 * dinv, bf16x2 pairs

// u = {hi: bf16(hiF), lo: bf16(loF)}
#define BF16X2(u, hiF, loF) asm("cvt.rn.bf16x2.f32 %0, %1, %2;" : "=r"(u) : "f"(hiF), "f"(loF))
#define TF32(u, f) asm("cvt.rna.tf32.f32 %0, %1;" : "=r"(u) : "f"(f))

// 1) degree histogram on dst (REDG, no return); 2 edges/thread (best measured)
__global__ void k_deg(const int* __restrict__ ei) {
    int t = blockIdx.x * blockDim.x + threadIdx.x;
    if (t >= N_EDGES / 2) return;
    int2 d = ((const int2*)(ei + N_EDGES))[t];
    atomicAdd(&g_deg[d.x], 1);
    atomicAdd(&g_deg[d.y], 1);
}

// 2) row allocation (warp scan + 1 atomic/warp) + dinv + premultiplied xw
__global__ void k_assign(const float* __restrict__ x) {
    int i = blockIdx.x * blockDim.x + threadIdx.x;
    int lane = threadIdx.x & 31;
    int deg = (i < N_NODES) ? g_deg[i] : 0;
    int incl = deg;
    #pragma unroll
    for (int o = 1; o < 32; o <<= 1) {
        int v = __shfl_up_sync(0xffffffff, incl, o);
        if (lane >= o) incl += v;
    }
    int base = 0;
    if (lane == 31) base = atomicAdd(&g_total, incl);   // incl@31 = warp total
    base = __shfl_sync(0xffffffff, base, 31);
    if (i < N_NODES) {
        int rs = base + incl - deg;
        g_rowstart[i] = rs;
        g_wpos[i] = rs;
        float dd = rsqrtf((float)(deg + 1));
        g_dinv[i] = dd;
        float4 xw;
        xw.x = __ldg(&x[i * 3 + 0]) * dd;
        xw.y = __ldg(&x[i * 3 + 1]) * dd;
        xw.z = __ldg(&x[i * 3 + 2]) * dd;
        xw.w = 0.f;
        ((float4*)g_xw)[i] = xw;
    }
}

// 3) FUSED CSR scatter + layer-1 scatter-aggregation (order-free v4 REDs)
__global__ void k_csr(const int* __restrict__ ei) {
    int t = blockIdx.x * blockDim.x + threadIdx.x;
    if (t >= N_EDGES / 2) return;
    int2 s = ((const int2*)ei)[t];
    int2 d = ((const int2*)(ei + N_EDGES))[t];
    int p0 = atomicAdd(&g_wpos[d.x], 1);
    int p1 = atomicAdd(&g_wpos[d.y], 1);
    float4 v0 = ((const float4*)g_xw)[s.x];
    float4 v1 = ((const float4*)g_xw)[s.y];
    g_csrc[p0] = s.x;
    g_csrc[p1] = s.y;
    float* q0 = g_v + (size_t)d.x * 4;
    float* q1 = g_v + (size_t)d.y * 4;
    asm volatile("red.global.add.v4.f32 [%0], {%1,%2,%3,%4};"
                 :: "l"(q0), "f"(v0.x), "f"(v0.y), "f"(v0.z), "f"(0.f) : "memory");
    asm volatile("red.global.add.v4.f32 [%0], {%1,%2,%3,%4};"
                 :: "l"(q1), "f"(v1.x), "f"(v1.y), "f"(v1.z), "f"(0.f) : "memory");
}

// 4) TENSOR-CORE h2: v=(g_v+xw_self)*dinv; h1 = relu(v@W1+b1) staged in
//    A-fragment layout (tf32, two 64-k chunks); h2 = h1 @ tf32(W2) via
//    mma.sync.m16n8k8; epilogue packs h2*dinv to bf16 pairs.
//    Warp w owns nodes [128b + 16w, 128b + 16w + 16), all 64 cols.
__global__ void __launch_bounds__(256, 3) k_h2(const float* __restrict__ W1,
                                               const float* __restrict__ b1,
                                               const float* __restrict__ W2) {
    __shared__ uint32_t sB[16 * 8 * 32 * 2];   // 32 KB  [kstep][ntile][lane][reg]
    __shared__ uint32_t sA[8 * 8 * 32 * 4];    // 32 KB  [mtile][ks][lane][reg]
    __shared__ float4   sv[128];               // 2 KB
    int tid  = threadIdx.x;
    int lane = tid & 31;
    int wid  = tid >> 5;                       // mtile
    int nodeBase = blockIdx.x * 128;

    // stage B = tf32(W2) in m16n8k8 B-fragment order
    // b_reg: k = kstep*8 + (lane&3) + 4*reg, n = ntile*8 + (lane>>2)
    for (int idx = tid; idx < 8192; idx += 256) {
        int kstep = idx >> 9;
        int ntile = (idx >> 6) & 7;
        int ln    = (idx >> 1) & 31;
        int reg   = idx & 1;
        int k = kstep * 8 + (ln & 3) + reg * 4;
        int n = ntile * 8 + (ln >> 2);
        uint32_t u;
        TF32(u, W2[k * 64 + n]);
        sB[idx] = u;
    }

    if (tid < 128) {                    // finalize layer-1 vector per node
        int gnode = nodeBase + tid;     // pad nodes: all zeros -> sv = 0
        float4 gv = ((const float4*)g_v)[gnode];
        float4 xs = ((const float4*)g_xw)[gnode];
        float dd  = g_dinv[gnode];
        sv[tid] = make_float4((gv.x + xs.x) * dd,
                              (gv.y + xs.y) * dd,
                              (gv.z + xs.z) * dd, 0.f);
    }
    __syncthreads();

    float acc[8][4];
    #pragma unroll
    for (int nt = 0; nt < 8; nt++)
        #pragma unroll
        for (int r = 0; r < 4; r++) acc[nt][r] = 0.f;

    #pragma unroll
    for (int chunk = 0; chunk < 2; chunk++) {
        // stage h1 (tf32) for k in [chunk*64, chunk*64+64) into A-frag layout
        // A-frag: a_reg = (r>=8) + 2*(kk>=4); lane = (r&7)*4 + (kk&3)
        #pragma unroll 2
        for (int i = tid; i < 128 * 16; i += 256) {
            int node = i & 127;
            int ql   = i >> 7;              // local quad 0..15
            int q    = chunk * 16 + ql;     // global quad
            float4 v  = sv[node];
            float4 w0 = __ldg(&((const float4*)W1)[0 * 32 + q]);
            float4 w1 = __ldg(&((const float4*)W1)[1 * 32 + q]);
            float4 w2 = __ldg(&((const float4*)W1)[2 * 32 + q]);
            float4 bq = __ldg(&((const float4*)b1)[q]);
            float h0 = fmaxf(fmaf(v.x, w0.x, fmaf(v.y, w1.x, fmaf(v.z, w2.x, bq.x))), 0.f);
            float h1 = fmaxf(fmaf(v.x, w0.y, fmaf(v.y, w1.y, fmaf(v.z, w2.y, bq.y))), 0.f);
            float h2 = fmaxf(fmaf(v.x, w0.z, fmaf(v.y, w1.z, fmaf(v.z, w2.z, bq.z))), 0.f);
            float h3 = fmaxf(fmaf(v.x, w0.w, fmaf(v.y, w1.w, fmaf(v.z, w2.w, bq.w))), 0.f);
            int r     = node & 15;
            int mtile = node >> 4;
            int ks    = ql >> 1;            // local kstep 0..7
            int regb  = ((r >= 8) ? 1 : 0) + ((ql & 1) ? 2 : 0);
            uint32_t base = ((mtile * 8 + ks) * 32 + (r & 7) * 4) * 4 + regb;
            uint32_t u0, u1, u2, u3;
            TF32(u0, h0);
            TF32(u1, h1);
            TF32(u2, h2);
            TF32(u3, h3);
            sA[base + 0]  = u0;     // j=0..3 -> lane + j -> +4 per j
            sA[base + 4]  = u1;
            sA[base + 8]  = u2;
            sA[base + 12] = u3;
        }
        __syncthreads();

        // mma mainloop over this chunk's 8 ksteps
        #pragma unroll
        for (int ks = 0; ks < 8; ks++) {
            uint4 av = *(const uint4*)&sA[((wid * 8 + ks) * 32 + lane) * 4];
            int kg = chunk * 8 + ks;
            #pragma unroll
            for (int nt = 0; nt < 8; nt++) {
                uint2 bv = *(const uint2*)&sB[((kg * 8 + nt) * 32 + lane) * 2];
                asm volatile(
                    "mma.sync.aligned.m16n8k8.row.col.f32.tf32.tf32.f32 "
                    "{%0,%1,%2,%3}, {%4,%5,%6,%7}, {%8,%9}, {%0,%1,%2,%3};"
                    : "+f"(acc[nt][0]), "+f"(acc[nt][1]),
                      "+f"(acc[nt][2]), "+f"(acc[nt][3])
                    : "r"(av.x), "r"(av.y), "r"(av.z), "r"(av.w),
                      "r"(bv.x), "r"(bv.y));
            }
        }
        __syncthreads();    // sA reused next chunk
    }

    // epilogue: C-frag (c0,c1)=(row g, cols 2t,2t+1), (c2,c3)=(row g+8, same)
    int g   = lane >> 2;
    int tig = lane & 3;
    int n0 = nodeBase + wid * 16 + g;
    int n1 = n0 + 8;
    float d0 = g_dinv[n0];
    float d1 = g_dinv[n1];
    #pragma unroll
    for (int nt = 0; nt < 8; nt++) {
        uint32_t u0, u1;
        BF16X2(u0, acc[nt][1] * d0, acc[nt][0] * d0);
        BF16X2(u1, acc[nt][3] * d1, acc[nt][2] * d1);
        g_h2wb[(size_t)n0 * 32 + nt * 4 + tig] = u0;
        g_h2wb[(size_t)n1 * 32 + nt * 4 + tig] = u1;
    }
}

// 5) layer-2 gather in bf16: 8 threads/node, each owns 8 cols (uint4 = 16B).
//    out = dinv[d]*(sum h2w[s] + h2w[d]) + b2. Resets deg/total/v for replay.
__global__ void k_gather2(const float* __restrict__ b2,
                          float* __restrict__ out) {
    int gid = blockIdx.x * blockDim.x + threadIdx.x;
    int node = gid >> 3;
    int q    = gid & 7;                 // uint32 words 4q..4q+3 = cols 8q..8q+7
    if (node >= N_NODES) return;
    int row = g_rowstart[node];
    int deg = g_deg[node];
    int end = row + deg;
    if (q == 0) {                       // reset for next call
        g_deg[node] = 0;
        ((float4*)g_v)[node] = make_float4(0.f, 0.f, 0.f, 0.f);
    }
    if (gid == 0) g_total = 0;

    float a[8];
    {   // self term
        uint4 u = *(const uint4*)&g_h2wb[(size_t)node * 32 + 4 * q];
        a[0] = __uint_as_float(u.x << 16);
        a[1] = __uint_as_float(u.x & 0xFFFF0000u);
        a[2] = __uint_as_float(u.y << 16);
        a[3] = __uint_as_float(u.y & 0xFFFF0000u);
        a[4] = __uint_as_float(u.z << 16);
        a[5] = __uint_as_float(u.z & 0xFFFF0000u);
        a[6] = __uint_as_float(u.w << 16);
        a[7] = __uint_as_float(u.w & 0xFFFF0000u);
    }
    int e = row;
    for (; e + 2 <= end; e += 2) {
        int s0 = g_csrc[e];
        int s1 = g_csrc[e + 1];
        uint4 u0 = *(const uint4*)&g_h2wb[(size_t)s0 * 32 + 4 * q];
        uint4 u1 = *(const uint4*)&g_h2wb[(size_t)s1 * 32 + 4 * q];
        a[0] += __uint_as_float(u0.x << 16)         + __uint_as_float(u1.x << 16);
        a[1] += __uint_as_float(u0.x & 0xFFFF0000u) + __uint_as_float(u1.x & 0xFFFF0000u);
        a[2] += __uint_as_float(u0.y << 16)         + __uint_as_float(u1.y << 16);
        a[3] += __uint_as_float(u0.y & 0xFFFF0000u) + __uint_as_float(u1.y & 0xFFFF0000u);
        a[4] += __uint_as_float(u0.z << 16)         + __uint_as_float(u1.z << 16);
        a[5] += __uint_as_float(u0.z & 0xFFFF0000u) + __uint_as_float(u1.z & 0xFFFF0000u);
        a[6] += __uint_as_float(u0.w << 16)         + __uint_as_float(u1.w << 16);
        a[7] += __uint_as_float(u0.w & 0xFFFF0000u) + __uint_as_float(u1.w & 0xFFFF0000u);
    }
    if (e < end) {
        uint4 u = *(const uint4*)&g_h2wb[(size_t)g_csrc[e] * 32 + 4 * q];
        a[0] += __uint_as_float(u.x << 16);
        a[1] += __uint_as_float(u.x & 0xFFFF0000u);
        a[2] += __uint_as_float(u.y << 16);
        a[3] += __uint_as_float(u.y & 0xFFFF0000u);
        a[4] += __uint_as_float(u.z << 16);
        a[5] += __uint_as_float(u.z & 0xFFFF0000u);
        a[6] += __uint_as_float(u.w << 16);
        a[7] += __uint_as_float(u.w & 0xFFFF0000u);
    }
    float dd = g_dinv[node];
    float4 bb0 = __ldg(&((const float4*)b2)[2 * q]);
    float4 bb1 = __ldg(&((const float4*)b2)[2 * q + 1]);
    float4 o0, o1;
    o0.x = fmaf(dd, a[0], bb0.x);
    o0.y = fmaf(dd, a[1], bb0.y);
    o0.z = fmaf(dd, a[2], bb0.z);
    o0.w = fmaf(dd, a[3], bb0.w);
    o1.x = fmaf(dd, a[4], bb1.x);
    o1.y = fmaf(dd, a[5], bb1.y);
    o1.z = fmaf(dd, a[6], bb1.z);
    o1.w = fmaf(dd, a[7], bb1.w);
    ((float4*)out)[(size_t)node * 16 + 2 * q] = o0;
    ((float4*)out)[(size_t)node * 16 + 2 * q + 1] = o1;
}

extern "C" void kernel_launch(void* const* d_in, const int* in_sizes, int n_in,
                              void* d_out, int out_size) {
    const float* x  = (const float*)d_in[0];
    const int*   ei = (const int*)d_in[1];   // int64 in ref -> int32 on device (JAX x64 off)
    const float* W1 = (const float*)d_in[2];
    const float* b1 = (const float*)d_in[3];
    const float* W2 = (const float*)d_in[4];
    const float* b2 = (const float*)d_in[5];
    float* out = (float*)d_out;

    k_deg<<<(N_EDGES / 2 + 255) / 256, 256>>>(ei);
    k_assign<<<(N_NODES + 255) / 256, 256>>>(x);
    k_csr<<<(N_EDGES / 2 + 255) / 256, 256>>>(ei);
    k_h2<<<N_PAD / 128, 256>>>(W1, b1, W2);
    k_gather2<<<(N_NODES * 8 + 255) / 256, 256>>>(b2, out);
}

// round 17
// speedup vs baseline: 1.2735x; 1.1752x over previous
#include <cuda_runtime.h>
#include <stdint.h>

#define N_NODES 50000
#define N_PAD   50048   // multiple of 128 for k_h2 tiling
#define N_EDGES 800000
#define HID     128
#define OUTC    64

// ---- scratch (device globals, zero-initialized at module load; k_gather2
//      re-zeroes g_deg/g_total/g_v each call so every replay starts clean).
//      Node arrays padded to N_PAD; pad entries stay 0. ----
__device__ int   g_deg[N_PAD];
__device__ int   g_rowstart[N_PAD];
__device__ int   g_wpos[N_PAD];
__device__ int   g_csrc[N_EDGES];
__device__ int   g_total;
__device__ float g_dinv[N_PAD];
__device__ __align__(16) float    g_xw[N_PAD * 4];     // x * dinv, packed float4
__device__ __align__(16) float    g_v[N_PAD * 4];      // layer-1 edge sums (RED target)
__device__ __align__(16) uint32_t g_h2wb[N_PAD * 32];  // h2 * dinv, bf16x2 pairs

// u = {hi: bf16(hiF), lo: bf16(loF)}
#define BF16X2(u, hiF, loF) asm("cvt.rn.bf16x2.f32 %0, %1, %2;" : "=r"(u) : "f"(hiF), "f"(loF))
#define TF32(u, f) asm("cvt.rna.tf32.f32 %0, %1;" : "=r"(u) : "f"(f))

// 1) degree histogram on dst (REDG, no return); 2 edges/thread (best measured)
__global__ void k_deg(const int* __restrict__ ei) {
    int t = blockIdx.x * blockDim.x + threadIdx.x;
    if (t >= N_EDGES / 2) return;
    int2 d = ((const int2*)(ei + N_EDGES))[t];
    atomicAdd(&g_deg[d.x], 1);
    atomicAdd(&g_deg[d.y], 1);
}

// 2) row allocation (warp scan + 1 atomic/warp) + dinv + premultiplied xw
__global__ void k_assign(const float* __restrict__ x) {
    int i = blockIdx.x * blockDim.x + threadIdx.x;
    int lane = threadIdx.x & 31;
    int deg = (i < N_NODES) ? g_deg[i] : 0;
    int incl = deg;
    #pragma unroll
    for (int o = 1; o < 32; o <<= 1) {
        int v = __shfl_up_sync(0xffffffff, incl, o);
        if (lane >= o) incl += v;
    }
    int base = 0;
    if (lane == 31) base = atomicAdd(&g_total, incl);   // incl@31 = warp total
    base = __shfl_sync(0xffffffff, base, 31);
    if (i < N_NODES) {
        int rs = base + incl - deg;
        g_rowstart[i] = rs;
        g_wpos[i] = rs;
        float dd = rsqrtf((float)(deg + 1));
        g_dinv[i] = dd;
        float4 xw;
        xw.x = __ldg(&x[i * 3 + 0]) * dd;
        xw.y = __ldg(&x[i * 3 + 1]) * dd;
        xw.z = __ldg(&x[i * 3 + 2]) * dd;
        xw.w = 0.f;
        ((float4*)g_xw)[i] = xw;
    }
}

// 3) FUSED CSR scatter + layer-1 scatter-aggregation (order-free v4 REDs)
__global__ void k_csr(const int* __restrict__ ei) {
    int t = blockIdx.x * blockDim.x + threadIdx.x;
    if (t >= N_EDGES / 2) return;
    int2 s = ((const int2*)ei)[t];
    int2 d = ((const int2*)(ei + N_EDGES))[t];
    int p0 = atomicAdd(&g_wpos[d.x], 1);
    int p1 = atomicAdd(&g_wpos[d.y], 1);
    float4 v0 = ((const float4*)g_xw)[s.x];
    float4 v1 = ((const float4*)g_xw)[s.y];
    g_csrc[p0] = s.x;
    g_csrc[p1] = s.y;
    float* q0 = g_v + (size_t)d.x * 4;
    float* q1 = g_v + (size_t)d.y * 4;
    asm volatile("red.global.add.v4.f32 [%0], {%1,%2,%3,%4};"
                 :: "l"(q0), "f"(v0.x), "f"(v0.y), "f"(v0.z), "f"(0.f) : "memory");
    asm volatile("red.global.add.v4.f32 [%0], {%1,%2,%3,%4};"
                 :: "l"(q1), "f"(v1.x), "f"(v1.y), "f"(v1.z), "f"(0.f) : "memory");
}

// 4) TENSOR-CORE h2, registers-only A path:
//    v=(g_v+xw_self)*dinv (sv, smem); h1 A-fragments computed IN REGISTERS
//    per lane from sv + W1T (h1[n][k] = relu(sv[n]·W1T[k]) — each (n,k)
//    computed exactly once, by the lane that owns it in the fragment map);
//    h2 = h1 @ tf32(W2) via mma.sync.m16n8k8; epilogue packs h2*dinv bf16.
//    smem = sB 32KB + W1T 2KB + sv 2KB; ONE barrier; no sA.
__global__ void __launch_bounds__(256) k_h2(const float* __restrict__ W1,
                                            const float* __restrict__ b1,
                                            const float* __restrict__ W2) {
    __shared__ uint32_t sB[16 * 8 * 32 * 2];   // 32 KB  [kstep][ntile][lane][reg]
    __shared__ float4   sW1T[HID];             // 2 KB   (W1[0][k],W1[1][k],W1[2][k],b1[k])
    __shared__ float4   sv[128];               // 2 KB
    int tid  = threadIdx.x;
    int lane = tid & 31;
    int wid  = tid >> 5;                       // mtile: nodes 16*wid..16*wid+15
    int nodeBase = blockIdx.x * 128;

    // stage B = tf32(W2) in m16n8k8 B-fragment order
    // b_reg: k = kstep*8 + (lane&3) + 4*reg, n = ntile*8 + (lane>>2)
    for (int idx = tid; idx < 8192; idx += 256) {
        int kstep = idx >> 9;
        int ntile = (idx >> 6) & 7;
        int ln    = (idx >> 1) & 31;
        int reg   = idx & 1;
        int k = kstep * 8 + (ln & 3) + reg * 4;
        int n = ntile * 8 + (ln >> 2);
        uint32_t u;
        TF32(u, W2[k * 64 + n]);
        sB[idx] = u;
    }

    if (tid < 128) {                    // W1 transposed + bias, one float4 per k
        sW1T[tid] = make_float4(W1[tid], W1[128 + tid], W1[256 + tid], b1[tid]);
    } else if (tid < 256) {             // finalize layer-1 vector per node
        int node  = tid - 128;
        int gnode = nodeBase + node;    // pad nodes: all zeros -> sv = 0
        float4 gv = ((const float4*)g_v)[gnode];
        float4 xs = ((const float4*)g_xw)[gnode];
        float dd  = g_dinv[gnode];
        sv[node] = make_float4((gv.x + xs.x) * dd,
                               (gv.y + xs.y) * dd,
                               (gv.z + xs.z) * dd, 0.f);
    }
    __syncthreads();

    int grp   = lane >> 2;              // row group 0..7
    int lane4 = lane & 3;               // k sub-index 0..3
    float4 v0 = sv[wid * 16 + grp];     // row grp      (loop-invariant)
    float4 v1 = sv[wid * 16 + grp + 8]; // row grp + 8

    float acc[8][4];
    #pragma unroll
    for (int nt = 0; nt < 8; nt++)
        #pragma unroll
        for (int r = 0; r < 4; r++) acc[nt][r] = 0.f;

    #pragma unroll
    for (int ks = 0; ks < 16; ks++) {
        float4 wa = sW1T[ks * 8 + lane4];       // k = 8ks + lane4
        float4 wb = sW1T[ks * 8 + lane4 + 4];   // k = 8ks + lane4 + 4
        // A-fragment values, each (node,k) computed by its owning lane
        float h0 = fmaxf(fmaf(v0.x, wa.x, fmaf(v0.y, wa.y, fmaf(v0.z, wa.z, wa.w))), 0.f);
        float h1 = fmaxf(fmaf(v1.x, wa.x, fmaf(v1.y, wa.y, fmaf(v1.z, wa.z, wa.w))), 0.f);
        float h2 = fmaxf(fmaf(v0.x, wb.x, fmaf(v0.y, wb.y, fmaf(v0.z, wb.z, wb.w))), 0.f);
        float h3 = fmaxf(fmaf(v1.x, wb.x, fmaf(v1.y, wb.y, fmaf(v1.z, wb.z, wb.w))), 0.f);
        uint32_t a0, a1, a2, a3;
        TF32(a0, h0);
        TF32(a1, h1);
        TF32(a2, h2);
        TF32(a3, h3);
        #pragma unroll
        for (int nt = 0; nt < 8; nt++) {
            uint2 bv = *(const uint2*)&sB[((ks * 8 + nt) * 32 + lane) * 2];
            asm volatile(
                "mma.sync.aligned.m16n8k8.row.col.f32.tf32.tf32.f32 "
                "{%0,%1,%2,%3}, {%4,%5,%6,%7}, {%8,%9}, {%0,%1,%2,%3};"
                : "+f"(acc[nt][0]), "+f"(acc[nt][1]),
                  "+f"(acc[nt][2]), "+f"(acc[nt][3])
                : "r"(a0), "r"(a1), "r"(a2), "r"(a3),
                  "r"(bv.x), "r"(bv.y));
        }
    }

    // epilogue: C-frag (c0,c1)=(row g, cols 2t,2t+1), (c2,c3)=(row g+8, same)
    int tig = lane & 3;
    int n0 = nodeBase + wid * 16 + grp;
    int n1 = n0 + 8;
    float d0 = g_dinv[n0];
    float d1 = g_dinv[n1];
    #pragma unroll
    for (int nt = 0; nt < 8; nt++) {
        uint32_t u0, u1;
        BF16X2(u0, acc[nt][1] * d0, acc[nt][0] * d0);
        BF16X2(u1, acc[nt][3] * d1, acc[nt][2] * d1);
        g_h2wb[(size_t)n0 * 32 + nt * 4 + tig] = u0;
        g_h2wb[(size_t)n1 * 32 + nt * 4 + tig] = u1;
    }
}

// 5) layer-2 gather in bf16: 8 threads/node, each owns 8 cols (uint4 = 16B).
//    out = dinv[d]*(sum h2w[s] + h2w[d]) + b2. Resets deg/total/v for replay.
__global__ void k_gather2(const float* __restrict__ b2,
                          float* __restrict__ out) {
    int gid = blockIdx.x * blockDim.x + threadIdx.x;
    int node = gid >> 3;
    int q    = gid & 7;                 // uint32 words 4q..4q+3 = cols 8q..8q+7
    if (node >= N_NODES) return;
    int row = g_rowstart[node];
    int deg = g_deg[node];
    int end = row + deg;
    if (q == 0) {                       // reset for next call
        g_deg[node] = 0;
        ((float4*)g_v)[node] = make_float4(0.f, 0.f, 0.f, 0.f);
    }
    if (gid == 0) g_total = 0;

    float a[8];
    {   // self term
        uint4 u = *(const uint4*)&g_h2wb[(size_t)node * 32 + 4 * q];
        a[0] = __uint_as_float(u.x << 16);
        a[1] = __uint_as_float(u.x & 0xFFFF0000u);
        a[2] = __uint_as_float(u.y << 16);
        a[3] = __uint_as_float(u.y & 0xFFFF0000u);
        a[4] = __uint_as_float(u.z << 16);
        a[5] = __uint_as_float(u.z & 0xFFFF0000u);
        a[6] = __uint_as_float(u.w << 16);
        a[7] = __uint_as_float(u.w & 0xFFFF0000u);
    }
    int e = row;
    for (; e + 2 <= end; e += 2) {
        int s0 = g_csrc[e];
        int s1 = g_csrc[e + 1];
        uint4 u0 = *(const uint4*)&g_h2wb[(size_t)s0 * 32 + 4 * q];
        uint4 u1 = *(const uint4*)&g_h2wb[(size_t)s1 * 32 + 4 * q];
        a[0] += __uint_as_float(u0.x << 16)         + __uint_as_float(u1.x << 16);
        a[1] += __uint_as_float(u0.x & 0xFFFF0000u) + __uint_as_float(u1.x & 0xFFFF0000u);
        a[2] += __uint_as_float(u0.y << 16)         + __uint_as_float(u1.y << 16);
        a[3] += __uint_as_float(u0.y & 0xFFFF0000u) + __uint_as_float(u1.y & 0xFFFF0000u);
        a[4] += __uint_as_float(u0.z << 16)         + __uint_as_float(u1.z << 16);
        a[5] += __uint_as_float(u0.z & 0xFFFF0000u) + __uint_as_float(u1.z & 0xFFFF0000u);
        a[6] += __uint_as_float(u0.w << 16)         + __uint_as_float(u1.w << 16);
        a[7] += __uint_as_float(u0.w & 0xFFFF0000u) + __uint_as_float(u1.w & 0xFFFF0000u);
    }
    if (e < end) {
        uint4 u = *(const uint4*)&g_h2wb[(size_t)g_csrc[e] * 32 + 4 * q];
        a[0] += __uint_as_float(u.x << 16);
        a[1] += __uint_as_float(u.x & 0xFFFF0000u);
        a[2] += __uint_as_float(u.y << 16);
        a[3] += __uint_as_float(u.y & 0xFFFF0000u);
        a[4] += __uint_as_float(u.z << 16);
        a[5] += __uint_as_float(u.z & 0xFFFF0000u);
        a[6] += __uint_as_float(u.w << 16);
        a[7] += __uint_as_float(u.w & 0xFFFF0000u);
    }
    float dd = g_dinv[node];
    float4 bb0 = __ldg(&((const float4*)b2)[2 * q]);
    float4 bb1 = __ldg(&((const float4*)b2)[2 * q + 1]);
    float4 o0, o1;
    o0.x = fmaf(dd, a[0], bb0.x);
    o0.y = fmaf(dd, a[1], bb0.y);
    o0.z = fmaf(dd, a[2], bb0.z);
    o0.w = fmaf(dd, a[3], bb0.w);
    o1.x = fmaf(dd, a[4], bb1.x);
    o1.y = fmaf(dd, a[5], bb1.y);
    o1.z = fmaf(dd, a[6], bb1.z);
    o1.w = fmaf(dd, a[7], bb1.w);
    ((float4*)out)[(size_t)node * 16 + 2 * q] = o0;
    ((float4*)out)[(size_t)node * 16 + 2 * q + 1] = o1;
}

extern "C" void kernel_launch(void* const* d_in, const int* in_sizes, int n_in,
                              void* d_out, int out_size) {
    const float* x  = (const float*)d_in[0];
    const int*   ei = (const int*)d_in[1];   // int64 in ref -> int32 on device (JAX x64 off)
    const float* W1 = (const float*)d_in[2];
    const float* b1 = (const float*)d_in[3];
    const float* W2 = (const float*)d_in[4];
    const float* b2 = (const float*)d_in[5];
    float* out = (float*)d_out;

    k_deg<<<(N_EDGES / 2 + 255) / 256, 256>>>(ei);
    k_assign<<<(N_NODES + 255) / 256, 256>>>(x);
    k_csr<<<(N_EDGES / 2 + 255) / 256, 256>>>(ei);
    k_h2<<<N_PAD / 128, 256>>>(W1, b1, W2);
    k_gather2<<<(N_NODES * 8 + 255) / 256, 256>>>(b2, out);
}